// round 2
// baseline (speedup 1.0000x reference)
#include <cuda_runtime.h>
#include <math.h>

#define Bv 8
#define Cv 19
#define Hv 256
#define Wv 256
#define HW (Hv*Wv)
#define NPIX (Bv*HW)
#define ROWBLKS (Bv*Hv)        /* 2048 */
#define COLBLKS (Bv*(Wv/32))   /* 64   */

// Scratch (allocation-free rule: __device__ globals, zero-init at load,
// reset at end of each run by the final block -> deterministic per call)
__device__ float g_g2[NPIX];      // squared row distance
__device__ int   g_hasb[Bv];      // per-batch "has boundary"
__device__ float g_part[COLBLKS]; // column-block partials
__device__ int   g_done;          // row blocks completed
__device__ int   g_cdone;         // col blocks completed

__global__ __launch_bounds__(256) void k_fused(const float* __restrict__ x,
                                               const int*   __restrict__ tg,
                                               float* __restrict__ out) {
    // union'd shared: row path needs 4KB, col path needs 32*(256+1)*4 B
    __shared__ __align__(16) char smraw[32 * (Hv + 1) * 4];
    __shared__ float red[8];
    __shared__ int   s_last;

    int tid = threadIdx.x;
    int bid = blockIdx.x;

    if (bid >= COLBLKS) {
        // ================= ROW PHASE =================
        int r = bid - COLBLKS;          // 0..2047
        int b = r >> 8, h = r & 255;
        int* t0 = (int*)smraw;
        int* t1 = t0 + Wv;
        int* t2 = t1 + Wv;
        float* ds = (float*)(t2 + Wv);

        const int* tb = tg + b * HW;
        int hm = (h > 0)      ? h - 1 : 0;
        int hp = (h < Hv - 1) ? h + 1 : Hv - 1;
        t0[tid] = tb[hm * Wv + tid];
        t1[tid] = tb[h  * Wv + tid];
        t2[tid] = tb[hp * Wv + tid];
        __syncthreads();

        int jm = (tid > 0)      ? tid - 1 : 0;
        int jp = (tid < Wv - 1) ? tid + 1 : Wv - 1;
        int c = t1[tid];
        bool bnd = (t0[jm] != c) | (t0[tid] != c) | (t0[jp] != c)
                 | (t1[jm] != c) | (t1[jp] != c)
                 | (t2[jm] != c) | (t2[tid] != c) | (t2[jp] != c);
        ds[tid] = bnd ? 0.0f : 1.0e6f;   // INF matches reference cap

        if (__syncthreads_or((int)bnd)) {
            if (tid == 0) atomicOr(&g_hasb[b], 1);
        }

        // Exact 1D min-plus distance via bidirectional doubling (8 steps)
        #pragma unroll
        for (int s = 1; s < Wv; s <<= 1) {
            float v  = ds[tid];
            float a  = (tid >= s)      ? ds[tid - s] + (float)s : 3.0e6f;
            float bb = (tid + s < Wv)  ? ds[tid + s] + (float)s : 3.0e6f;
            __syncthreads();
            ds[tid] = fminf(v, fminf(a, bb));
            __syncthreads();
        }
        float rr = ds[tid];
        g_g2[r * Wv + tid] = rr * rr;

        __threadfence();     // publish g_g2 before signaling
        __syncthreads();
        if (tid == 0) atomicAdd(&g_done, 1);
        return;
    }

    // ================= COLUMN PHASE =================
    // Wait until all row blocks have published g_g2 / g_hasb.
    if (tid == 0) {
        while (*(volatile int*)&g_done < ROWBLKS) { }
    }
    __syncthreads();
    __threadfence();

    float (*g2s)[Hv + 1] = (float (*)[Hv + 1])smraw;   // [jj][i], pad-free banks

    int b  = bid >> 3;
    int j0 = (bid & 7) << 5;

    const float* g2b = g_g2 + b * HW;
    for (int p = tid; p < 32 * Hv; p += 256) {
        int i = p >> 5, jj = p & 31;
        g2s[jj][i] = __ldcg(&g2b[i * Wv + j0 + jj]);    // L2 read (fresh data)
    }
    __syncthreads();

    int hasb = *(volatile int*)&g_hasb[b];
    const float* xb0 = x + (size_t)b * Cv * HW;
    const int*   tb  = tg + b * HW;
    float acc = 0.0f;

    for (int mq = 0; mq < 32; ++mq) {
        int p  = mq * 256 + tid;
        int i  = p >> 5;        // same i across a warp
        int jj = p & 31;        // jj == lane -> conflict-free smem

        // exact column EDT via pruned outward scan
        float best = g2s[jj][i];
        for (int d = 1; d < Hv; ++d) {
            float c2 = (float)(d * d);
            if (c2 >= best) break;
            int lo = i - d, hi = i + d;
            if (lo >= 0) best = fminf(best, c2 + g2s[jj][lo]);
            if (hi < Hv) best = fminf(best, c2 + g2s[jj][hi]);
        }
        float w = hasb ? __expf(-sqrtf(best) * 0.2f) : 1.0f;

        // fused CE (log-softmax over 19 channels, coalesced 128B per channel)
        const float* xp = xb0 + i * Wv + j0 + jj;
        float xv[Cv];
        #pragma unroll
        for (int q = 0; q < Cv; ++q) xv[q] = xp[(size_t)q * HW];
        float m = xv[0];
        #pragma unroll
        for (int q = 1; q < Cv; ++q) m = fmaxf(m, xv[q]);
        float s = 0.0f;
        #pragma unroll
        for (int q = 0; q < Cv; ++q) s += __expf(xv[q] - m);
        float lse = m + __logf(s);
        int c = tb[i * Wv + j0 + jj];
        float xt = xp[(size_t)c * HW];    // L1 hit (just loaded)
        acc += w * (lse - xt);
    }

    // deterministic block reduce
    #pragma unroll
    for (int o = 16; o > 0; o >>= 1)
        acc += __shfl_down_sync(0xffffffffu, acc, o);
    if ((tid & 31) == 0) red[tid >> 5] = acc;
    __syncthreads();

    if (tid == 0) {
        float v = 0.0f;
        #pragma unroll
        for (int q = 0; q < 8; ++q) v += red[q];
        g_part[bid] = v;
        __threadfence();
        int prev = atomicAdd(&g_cdone, 1);
        s_last = (prev == COLBLKS - 1);
    }
    __syncthreads();

    if (s_last && tid == 0) {
        __threadfence();
        float v = 0.0f;
        for (int q = 0; q < COLBLKS; ++q) v += g_part[q];
        out[0] = v * (1.0f / (float)NPIX);
        // reset scratch state for the next (graph-replayed) call
        g_done = 0;
        g_cdone = 0;
        #pragma unroll
        for (int q = 0; q < Bv; ++q) g_hasb[q] = 0;
        __threadfence();
    }
}

extern "C" void kernel_launch(void* const* d_in, const int* in_sizes, int n_in,
                              void* d_out, int out_size) {
    const float* x  = (const float*)d_in[0];
    const int*   tg = (const int*)d_in[1];
    if (n_in >= 2 && in_sizes[0] < in_sizes[1]) {   // robustness: pick by size
        x  = (const float*)d_in[1];
        tg = (const int*)d_in[0];
    }
    k_fused<<<ROWBLKS + COLBLKS, 256>>>(x, tg, (float*)d_out);
}

// round 3
// speedup vs baseline: 1.3754x; 1.3754x over previous
#include <cuda_runtime.h>
#include <math.h>

#define Bv 8
#define Cv 19
#define Hv 256
#define Wv 256
#define HW (Hv*Wv)
#define NPIX (Bv*HW)
#define ROWBLKS (Bv*Hv)          /* 2048 */
#define TILEW 16
#define COLBLKS (Bv*(Wv/TILEW)) /* 128 */

// Scratch (__device__ globals; zero at load; K2's last block resets mutable
// state -> every graph replay sees identical initial state)
__device__ float g_g2[NPIX];       // squared row distance
__device__ int   g_hasb[Bv];       // per-batch "has boundary"
__device__ float g_part[COLBLKS];  // block partials
__device__ int   g_cdone;          // ticket counter

// ---------------- K1: boundary + exact 1D row distance ----------------
__global__ __launch_bounds__(256) void k_row(const int* __restrict__ tg) {
    __shared__ int t0[Wv], t1[Wv], t2[Wv];
    __shared__ float ds[Wv];

    int r = blockIdx.x;            // 0..2047
    int b = r >> 8, h = r & 255;
    int j = threadIdx.x;

    const int* tb = tg + b * HW;
    int hm = (h > 0)      ? h - 1 : 0;
    int hp = (h < Hv - 1) ? h + 1 : Hv - 1;
    t0[j] = tb[hm * Wv + j];
    t1[j] = tb[h  * Wv + j];
    t2[j] = tb[hp * Wv + j];
    __syncthreads();

    int jm = (j > 0)      ? j - 1 : 0;
    int jp = (j < Wv - 1) ? j + 1 : Wv - 1;
    int c = t1[j];
    bool bnd = (t0[jm] != c) | (t0[j] != c) | (t0[jp] != c)
             | (t1[jm] != c) | (t1[jp] != c)
             | (t2[jm] != c) | (t2[j] != c) | (t2[jp] != c);
    ds[j] = bnd ? 0.0f : 1.0e6f;   // INF cap matches reference

    if (__syncthreads_or((int)bnd)) {
        if (j == 0) atomicOr(&g_hasb[b], 1);
    }

    // exact 1D min-plus distance: bidirectional doubling, 8 steps
    #pragma unroll
    for (int s = 1; s < Wv; s <<= 1) {
        float v  = ds[j];
        float a  = (j >= s)     ? ds[j - s] + (float)s : 3.0e6f;
        float bb = (j + s < Wv) ? ds[j + s] + (float)s : 3.0e6f;
        __syncthreads();
        ds[j] = fminf(v, fminf(a, bb));
        __syncthreads();
    }
    float rr = ds[j];
    g_g2[r * Wv + j] = rr * rr;
}

// ---- K2: column EDT (pruned exact) + fused CE + deterministic reduce ----
__global__ __launch_bounds__(256) void k_colce(const float* __restrict__ x,
                                               const int*   __restrict__ tg,
                                               float* __restrict__ out) {
    __shared__ float g2s[Hv][TILEW];   // i*16+jj -> warp spans 32 consecutive words
    __shared__ float red[8];
    __shared__ int   s_last;

    int bid = blockIdx.x, tid = threadIdx.x;
    int b  = bid >> 4;                 // 16 tiles per batch
    int j0 = (bid & 15) * TILEW;

    const float* g2b = g_g2 + b * HW;
    for (int p = tid; p < Hv * TILEW; p += 256) {
        int i = p >> 4, jj = p & 15;
        g2s[i][jj] = g2b[i * Wv + j0 + jj];
    }
    __syncthreads();

    int hasb = g_hasb[b];
    const float* xb0 = x + (size_t)b * Cv * HW;
    const int*   tb  = tg + b * HW;
    float acc = 0.0f;

    #pragma unroll 1
    for (int it = 0; it < TILEW; ++it) {
        int p  = it * 256 + tid;
        int i  = p >> 4;               // 2 rows per warp
        int jj = p & 15;

        float w = 1.0f;
        if (hasb) {
            // exact column EDT: outward scan, prune when (d)^2 >= best
            float best = g2s[i][jj];
            for (int d = 1; d < Hv; ++d) {
                float c2 = (float)(d * d);
                if (c2 >= best) break;
                int lo = i - d, hi = i + d;
                if (lo >= 0) best = fminf(best, c2 + g2s[lo][jj]);
                if (hi < Hv) best = fminf(best, c2 + g2s[hi][jj]);
            }
            w = __expf(-sqrtf(best) * 0.2f);   // sigma = 5
        }

        // fused CE: log-softmax over 19 channels (2x64B sectors per warp-load)
        const float* xp = xb0 + i * Wv + j0 + jj;
        float xv[Cv];
        #pragma unroll
        for (int q = 0; q < Cv; ++q) xv[q] = xp[(size_t)q * HW];
        float m = xv[0];
        #pragma unroll
        for (int q = 1; q < Cv; ++q) m = fmaxf(m, xv[q]);
        float s = 0.0f;
        #pragma unroll
        for (int q = 0; q < Cv; ++q) s += __expf(xv[q] - m);
        float lse = m + __logf(s);
        int c = tb[i * Wv + j0 + jj];
        float xt = xp[(size_t)c * HW];          // L1 hit
        acc += w * (lse - xt);
    }

    // deterministic block reduction
    #pragma unroll
    for (int o = 16; o > 0; o >>= 1)
        acc += __shfl_down_sync(0xffffffffu, acc, o);
    if ((tid & 31) == 0) red[tid >> 5] = acc;
    __syncthreads();

    if (tid == 0) {
        float v = 0.0f;
        #pragma unroll
        for (int q = 0; q < 8; ++q) v += red[q];
        g_part[bid] = v;
        __threadfence();
        int prev = atomicAdd(&g_cdone, 1);
        s_last = (prev == COLBLKS - 1);
    }
    __syncthreads();

    if (s_last) {
        __threadfence();
        // fixed-order tree over 128 partials -> deterministic
        float v = (tid < COLBLKS) ? __ldcg(&g_part[tid]) : 0.0f;
        #pragma unroll
        for (int o = 16; o > 0; o >>= 1)
            v += __shfl_down_sync(0xffffffffu, v, o);
        if ((tid & 31) == 0) red[tid >> 5] = v;
        __syncthreads();
        if (tid == 0) {
            float t = red[0] + red[1] + red[2] + red[3];
            out[0] = t * (1.0f / (float)NPIX);
            // reset state for next graph replay
            g_cdone = 0;
            #pragma unroll
            for (int q = 0; q < Bv; ++q) g_hasb[q] = 0;
            __threadfence();
        }
    }
}

extern "C" void kernel_launch(void* const* d_in, const int* in_sizes, int n_in,
                              void* d_out, int out_size) {
    const float* x  = (const float*)d_in[0];
    const int*   tg = (const int*)d_in[1];
    if (n_in >= 2 && in_sizes[0] < in_sizes[1]) {   // robustness: pick by size
        x  = (const float*)d_in[1];
        tg = (const int*)d_in[0];
    }
    k_row<<<ROWBLKS, 256>>>(tg);
    k_colce<<<COLBLKS, 256>>>(x, tg, (float*)d_out);
}

// round 5
// speedup vs baseline: 1.9633x; 1.4274x over previous
#include <cuda_runtime.h>
#include <math.h>

#define Bv 8
#define Cv 19
#define Hv 256
#define Wv 256
#define HW (Hv*Wv)
#define NPIX (Bv*HW)
#define ROWBLKS (Bv*Hv)          /* 2048 */
#define TILEW 16
#define COLBLKS (Bv*(Wv/TILEW)) /* 128 */
#define CTHREADS 1024

// Scratch (__device__ globals; zero at load; K2's last block resets mutable
// state -> every graph replay sees identical initial state)
__device__ float g_g2[NPIX];       // squared row distance
__device__ int   g_hasb[Bv];       // per-batch "has boundary"
__device__ float g_part[COLBLKS];  // block partials
__device__ int   g_cdone;          // ticket counter

// ---------------- K1: boundary + exact 1D row distance ----------------
__global__ __launch_bounds__(256) void k_row(const int* __restrict__ tg) {
    __shared__ int t0[Wv], t1[Wv], t2[Wv];
    __shared__ float ds[Wv];

    int r = blockIdx.x;            // 0..2047
    int b = r >> 8, h = r & 255;
    int j = threadIdx.x;

    const int* tb = tg + b * HW;
    int hm = (h > 0)      ? h - 1 : 0;
    int hp = (h < Hv - 1) ? h + 1 : Hv - 1;
    t0[j] = tb[hm * Wv + j];
    t1[j] = tb[h  * Wv + j];
    t2[j] = tb[hp * Wv + j];
    __syncthreads();

    int jm = (j > 0)      ? j - 1 : 0;
    int jp = (j < Wv - 1) ? j + 1 : Wv - 1;
    int c = t1[j];
    bool bnd = (t0[jm] != c) | (t0[j] != c) | (t0[jp] != c)
             | (t1[jm] != c) | (t1[jp] != c)
             | (t2[jm] != c) | (t2[j] != c) | (t2[jp] != c);
    ds[j] = bnd ? 0.0f : 1.0e6f;   // INF cap matches reference

    if (__syncthreads_or((int)bnd)) {
        if (j == 0) atomicOr(&g_hasb[b], 1);
    }

    // exact 1D min-plus distance: bidirectional doubling, 8 steps
    #pragma unroll
    for (int s = 1; s < Wv; s <<= 1) {
        float v  = ds[j];
        float a  = (j >= s)     ? ds[j - s] + (float)s : 3.0e6f;
        float bb = (j + s < Wv) ? ds[j + s] + (float)s : 3.0e6f;
        __syncthreads();
        ds[j] = fminf(v, fminf(a, bb));
        __syncthreads();
    }
    float rr = ds[j];
    g_g2[r * Wv + j] = rr * rr;
}

// ---- K2: column EDT (pruned exact) + fused CE + deterministic reduce ----
// 1024 threads/block: 32 resident warps/SM for DRAM latency hiding.
__global__ __launch_bounds__(CTHREADS) void k_colce(const float* __restrict__ x,
                                                    const int*   __restrict__ tg,
                                                    float* __restrict__ out) {
    __shared__ float g2s[Hv][TILEW];   // warp = 2 rows x 16 cols -> conflict-free
    __shared__ float red[32];
    __shared__ int   s_last;

    int bid = blockIdx.x, tid = threadIdx.x;
    int b  = bid >> 4;                 // 16 tiles per batch
    int j0 = (bid & 15) * TILEW;

    const float* g2b = g_g2 + b * HW;
    for (int p = tid; p < Hv * TILEW; p += CTHREADS) {
        int i = p >> 4, jj = p & 15;
        g2s[i][jj] = g2b[i * Wv + j0 + jj];
    }
    __syncthreads();

    int hasb = g_hasb[b];
    const float* xb0 = x + (size_t)b * Cv * HW;
    const int*   tb  = tg + b * HW;
    float acc = 0.0f;

    #pragma unroll 1
    for (int it = 0; it < (Hv * TILEW) / CTHREADS; ++it) {   // 4 iterations
        int p  = it * CTHREADS + tid;
        int i  = p >> 4;               // 2 rows per warp
        int jj = p & 15;

        float w = 1.0f;
        if (hasb) {
            // exact column EDT: outward scan, prune when d^2 >= best
            float best = g2s[i][jj];
            for (int d = 1; d < Hv; ++d) {
                float c2 = (float)(d * d);
                if (c2 >= best) break;
                int lo = i - d, hi = i + d;
                if (lo >= 0) best = fminf(best, c2 + g2s[lo][jj]);
                if (hi < Hv) best = fminf(best, c2 + g2s[hi][jj]);
            }
            w = __expf(-sqrtf(best) * 0.2f);   // sigma = 5
        }

        // fused CE: log-softmax over 19 channels
        const float* xp = xb0 + i * Wv + j0 + jj;
        float xv[Cv];
        #pragma unroll
        for (int q = 0; q < Cv; ++q) xv[q] = xp[(size_t)q * HW];
        float m = xv[0];
        #pragma unroll
        for (int q = 1; q < Cv; ++q) m = fmaxf(m, xv[q]);
        float s = 0.0f;
        #pragma unroll
        for (int q = 0; q < Cv; ++q) s += __expf(xv[q] - m);
        float lse = m + __logf(s);
        int c = tb[i * Wv + j0 + jj];
        float xt = xp[(size_t)c * HW];          // L1 hit
        acc += w * (lse - xt);
    }

    // deterministic block reduction (32 warps)
    #pragma unroll
    for (int o = 16; o > 0; o >>= 1)
        acc += __shfl_down_sync(0xffffffffu, acc, o);
    if ((tid & 31) == 0) red[tid >> 5] = acc;
    __syncthreads();

    if (tid == 0) {
        float v = 0.0f;
        #pragma unroll
        for (int q = 0; q < 32; ++q) v += red[q];
        g_part[bid] = v;
        __threadfence();
        int prev = atomicAdd(&g_cdone, 1);
        s_last = (prev == COLBLKS - 1);
    }
    __syncthreads();

    if (s_last) {
        __threadfence();
        // fixed-order tree over 128 partials -> deterministic
        float v = (tid < COLBLKS) ? __ldcg(&g_part[tid]) : 0.0f;
        #pragma unroll
        for (int o = 16; o > 0; o >>= 1)
            v += __shfl_down_sync(0xffffffffu, v, o);
        if ((tid & 31) == 0) red[tid >> 5] = v;
        __syncthreads();
        if (tid == 0) {
            float t = red[0] + red[1] + red[2] + red[3];
            out[0] = t * (1.0f / (float)NPIX);
            // reset state for next graph replay
            g_cdone = 0;
            #pragma unroll
            for (int q = 0; q < Bv; ++q) g_hasb[q] = 0;
            __threadfence();
        }
    }
}

extern "C" void kernel_launch(void* const* d_in, const int* in_sizes, int n_in,
                              void* d_out, int out_size) {
    const float* x  = (const float*)d_in[0];
    const int*   tg = (const int*)d_in[1];
    if (n_in >= 2 && in_sizes[0] < in_sizes[1]) {   // robustness: pick by size
        x  = (const float*)d_in[1];
        tg = (const int*)d_in[0];
    }
    k_row<<<ROWBLKS, 256>>>(tg);
    k_colce<<<COLBLKS, CTHREADS>>>(x, tg, (float*)d_out);
}